// round 1
// baseline (speedup 1.0000x reference)
#include <cuda_runtime.h>
#include <math.h>

#define BB 8
#define NN 4096
#define WW 64
#define RR 4
#define EPSC 1e-8f

// ---------------- scratch (no allocs allowed -> __device__ globals) ----------
__device__ __align__(16) float g_usage[BB*NN];
__device__ __align__(16) float g_zw[BB*NN];
__device__ __align__(16) float g_alloc[BB*NN];
__device__ __align__(16) float g_ww[BB*NN];
__device__ __align__(16) float g_memnew[BB*NN*WW];
__device__ __align__(16) float g_zr[BB*NN*RR];
__device__ __align__(16) float g_cbr[BB*NN*RR];
__device__ __align__(16) float g_fwd[BB*NN*RR];
__device__ __align__(16) float g_bwd[BB*NN*RR];

// ---------------- K1: new usage + write content scores; zero d_out -----------
__global__ void k1_usage_sim(const float* __restrict__ memory,
                             const float* __restrict__ write_key,
                             const float* __restrict__ write_strength,
                             const float* __restrict__ free_gates,
                             const float* __restrict__ read_weightings,
                             const float* __restrict__ write_weighting,
                             const float* __restrict__ memory_usage,
                             float* __restrict__ out) {
    const int b   = blockIdx.y;
    const int tid = threadIdx.x;
    const int n   = blockIdx.x * 256 + tid;
    __shared__ float wk_s[WW];
    __shared__ float fg_s[RR];
    __shared__ float wkn;
    if (tid < WW) wk_s[tid] = write_key[b*WW + tid];
    if (tid < RR) fg_s[tid] = free_gates[b*RR + tid];
    if (blockIdx.y == 0 && blockIdx.x < 8) out[blockIdx.x*256 + tid] = 0.0f;
    __syncthreads();
    if (tid == 0) {
        float s = 0.f;
        for (int w = 0; w < WW; w++) s += wk_s[w]*wk_s[w];
        wkn = sqrtf(s);
    }
    __syncthreads();

    const size_t bn = (size_t)b*NN + n;
    float u  = memory_usage[bn];
    float wv = write_weighting[bn];
    float uw = u + wv - u*wv;
    float4 rw = *(const float4*)(read_weightings + bn*RR);
    float prod = (1.f - rw.x*fg_s[0]) * (1.f - rw.y*fg_s[1])
               * (1.f - rw.z*fg_s[2]) * (1.f - rw.w*fg_s[3]);
    g_usage[bn] = uw * prod;

    const float4* mrow = (const float4*)(memory + bn*WW);
    float dot = 0.f, nrm = 0.f;
    #pragma unroll
    for (int i = 0; i < 16; i++) {
        float4 m = mrow[i];
        dot += m.x*wk_s[i*4+0] + m.y*wk_s[i*4+1] + m.z*wk_s[i*4+2] + m.w*wk_s[i*4+3];
        nrm += m.x*m.x + m.y*m.y + m.z*m.z + m.w*m.w;
    }
    float sim = dot / (wkn * sqrtf(nrm) + EPSC);
    g_zw[bn] = write_strength[b] * sim;
}

// ---------------- K2: per-batch sort -> allocation weights -------------------
__global__ void k2_alloc() {
    const int b   = blockIdx.x;
    const int tid = threadIdx.x;  // 512 threads
    __shared__ float sv[NN];
    __shared__ int   si[NN];
    __shared__ float cp[512];

    for (int i = tid; i < NN; i += 512) { sv[i] = g_usage[(size_t)b*NN + i]; si[i] = i; }
    __syncthreads();

    // bitonic sort ascending (matches jnp.argsort)
    for (int k = 2; k <= NN; k <<= 1) {
        for (int j = k >> 1; j > 0; j >>= 1) {
            for (int i = tid; i < NN; i += 512) {
                int ixj = i ^ j;
                if (ixj > i) {
                    bool up = ((i & k) == 0);
                    float a = sv[i], c = sv[ixj];
                    bool sw = up ? (a > c) : (a < c);
                    if (sw) {
                        sv[i] = c; sv[ixj] = a;
                        int t = si[i]; si[i] = si[ixj]; si[ixj] = t;
                    }
                }
            }
            __syncthreads();
        }
    }

    // chunked exclusive prefix product of sorted usage
    float p = 1.f;
    const int base = tid * 8;
    #pragma unroll
    for (int t = 0; t < 8; t++) p *= sv[base + t];
    cp[tid] = p;
    __syncthreads();
    for (int off = 1; off < 512; off <<= 1) {
        float v = cp[tid];
        float o = (tid >= off) ? cp[tid - off] : 1.f;
        __syncthreads();
        cp[tid] = v * o;
        __syncthreads();
    }
    float run = (tid == 0) ? 1.f : cp[tid - 1];
    #pragma unroll
    for (int t = 0; t < 8; t++) {
        float v = sv[base + t];
        g_alloc[(size_t)b*NN + si[base + t]] = (1.f - v) * run;  // (1-ordered)*cumprod(shifted)
        run *= v;
    }
}

// ---------------- K3: softmax(cbw) + final write weighting -------------------
__global__ void k3_ww(const float* __restrict__ allocation_gate,
                      const float* __restrict__ write_gate) {
    const int b   = blockIdx.x;
    const int tid = threadIdx.x;  // 1024
    __shared__ float sh[32];
    const size_t bo = (size_t)b*NN;

    float z[4];
    float lm = -3.4e38f;
    #pragma unroll
    for (int k = 0; k < 4; k++) { z[k] = g_zw[bo + tid + k*1024]; lm = fmaxf(lm, z[k]); }
    for (int o = 16; o; o >>= 1) lm = fmaxf(lm, __shfl_xor_sync(0xffffffffu, lm, o));
    if ((tid & 31) == 0) sh[tid >> 5] = lm;
    __syncthreads();
    if (tid < 32) {
        float v = sh[tid];
        for (int o = 16; o; o >>= 1) v = fmaxf(v, __shfl_xor_sync(0xffffffffu, v, o));
        if (tid == 0) sh[0] = v;
    }
    __syncthreads();
    const float bmax = sh[0];
    __syncthreads();

    float e[4], ls = 0.f;
    #pragma unroll
    for (int k = 0; k < 4; k++) { e[k] = expf(z[k] - bmax); ls += e[k]; }
    for (int o = 16; o; o >>= 1) ls += __shfl_xor_sync(0xffffffffu, ls, o);
    if ((tid & 31) == 0) sh[tid >> 5] = ls;
    __syncthreads();
    if (tid < 32) {
        float v = sh[tid];
        for (int o = 16; o; o >>= 1) v += __shfl_xor_sync(0xffffffffu, v, o);
        if (tid == 0) sh[0] = v;
    }
    __syncthreads();
    const float bsum = sh[0];

    const float ag = allocation_gate[b], wg = write_gate[b];
    #pragma unroll
    for (int k = 0; k < 4; k++) {
        size_t idx = bo + tid + k*1024;
        float cbw = e[k] / bsum;
        g_ww[idx] = wg * (ag * g_alloc[idx] + (1.f - ag) * cbw);
    }
}

// ---------------- K4: memory erase/write + read content scores --------------
__global__ void k4_memupdate(const float* __restrict__ memory,
                             const float* __restrict__ erase_vector,
                             const float* __restrict__ write_vector,
                             const float* __restrict__ read_keys,
                             const float* __restrict__ read_strengths) {
    const int b   = blockIdx.y;
    const int tid = threadIdx.x;
    const int n   = blockIdx.x * 256 + tid;
    __shared__ float rk_s[WW][RR];
    __shared__ float ev_s[WW], wv_s[WW];
    __shared__ float nrk_s[RR], rs_s[RR];

    if (tid < WW) { ev_s[tid] = erase_vector[b*WW + tid]; wv_s[tid] = write_vector[b*WW + tid]; }
    { int w = tid >> 2, r = tid & 3; rk_s[w][r] = read_keys[b*WW*RR + tid]; }
    __syncthreads();
    if (tid < RR) {
        float s = 0.f;
        for (int w = 0; w < WW; w++) { float v = rk_s[w][tid]; s += v*v; }
        nrk_s[tid] = sqrtf(s);
        rs_s[tid]  = read_strengths[b*RR + tid];
    }
    __syncthreads();

    const size_t bn = (size_t)b*NN + n;
    const float wwn = g_ww[bn];
    const float4* mrow = (const float4*)(memory + bn*WW);
    float4* orow = (float4*)(g_memnew + bn*WW);

    float nrm = 0.f, s0 = 0.f, s1 = 0.f, s2 = 0.f, s3 = 0.f;
    #pragma unroll
    for (int i = 0; i < 16; i++) {
        float4 m = mrow[i];
        float mv[4] = {m.x, m.y, m.z, m.w};
        float ov[4];
        #pragma unroll
        for (int c = 0; c < 4; c++) {
            int w = i*4 + c;
            ov[c] = fmaf(mv[c], 1.f - wwn*ev_s[w], wwn*wv_s[w]);
            nrm += ov[c]*ov[c];
            s0 = fmaf(ov[c], rk_s[w][0], s0);
            s1 = fmaf(ov[c], rk_s[w][1], s1);
            s2 = fmaf(ov[c], rk_s[w][2], s2);
            s3 = fmaf(ov[c], rk_s[w][3], s3);
        }
        float4 o4 = make_float4(ov[0], ov[1], ov[2], ov[3]);
        orow[i] = o4;
    }
    const float nn = sqrtf(nrm);
    float4 zr;
    zr.x = rs_s[0]*s0 / (nn*nrk_s[0] + EPSC);
    zr.y = rs_s[1]*s1 / (nn*nrk_s[1] + EPSC);
    zr.z = rs_s[2]*s2 / (nn*nrk_s[2] + EPSC);
    zr.w = rs_s[3]*s3 / (nn*nrk_s[3] + EPSC);
    *(float4*)(g_zr + bn*RR) = zr;
}

// ---------------- K5: softmax(cbr) per (b,r); zeroes fwd/bwd -----------------
__global__ void k5_cbr() {
    const int r = blockIdx.x, b = blockIdx.y;
    const int tid = threadIdx.x;  // 256
    __shared__ float sh[8];
    const size_t bo = (size_t)b*NN;

    float z[16];
    float lm = -3.4e38f;
    #pragma unroll
    for (int k = 0; k < 16; k++) {
        size_t idx = (bo + tid + (size_t)k*256)*RR + r;
        z[k] = g_zr[idx];
        g_fwd[idx] = 0.f;
        g_bwd[idx] = 0.f;
        lm = fmaxf(lm, z[k]);
    }
    for (int o = 16; o; o >>= 1) lm = fmaxf(lm, __shfl_xor_sync(0xffffffffu, lm, o));
    if ((tid & 31) == 0) sh[tid >> 5] = lm;
    __syncthreads();
    if (tid < 8) {
        float v = sh[tid];
        for (int o = 4; o; o >>= 1) v = fmaxf(v, __shfl_xor_sync(0xffu, v, o));
        if (tid == 0) sh[0] = v;
    }
    __syncthreads();
    const float bmax = sh[0];
    __syncthreads();

    float ls = 0.f;
    #pragma unroll
    for (int k = 0; k < 16; k++) { z[k] = expf(z[k] - bmax); ls += z[k]; }
    for (int o = 16; o; o >>= 1) ls += __shfl_xor_sync(0xffffffffu, ls, o);
    if ((tid & 31) == 0) sh[tid >> 5] = ls;
    __syncthreads();
    if (tid < 8) {
        float v = sh[tid];
        for (int o = 4; o; o >>= 1) v += __shfl_xor_sync(0xffu, v, o);
        if (tid == 0) sh[0] = v;
    }
    __syncthreads();
    const float bsum = sh[0];

    #pragma unroll
    for (int k = 0; k < 16; k++) {
        size_t idx = (bo + tid + (size_t)k*256)*RR + r;
        g_cbr[idx] = z[k] / bsum;
    }
}

// ---------------- K6: fused link update + fwd/bwd matvecs (single L pass) ----
// L'[n,m] = (1-ww_n-ww_m)*L[n,m] + ww_n*p_m, diag zeroed (never materialized)
// fwd[n,r] += L'[n,m]*rwo[m,r]   ;   bwd[m,r] += L'[n,m]*rwo[n,r]
__global__ void k6_link(const float* __restrict__ L,
                        const float* __restrict__ rwo,
                        const float* __restrict__ prec) {
    const int b    = blockIdx.z;
    const int n0   = blockIdx.y * 128;
    const int tid  = threadIdx.x;       // 256 = 8 warps
    const int warp = tid >> 5, lane = tid & 31;
    const int mb   = blockIdx.x * 1024 + warp * 128 + lane * 4;  // this lane's 4 columns
    const size_t bo = (size_t)b * NN;

    __shared__ float wwn_s[128];
    __shared__ __align__(16) float rwon_s[128][4];
    __shared__ __align__(16) float fwd_s[128][4];

    if (tid < 128) {
        wwn_s[tid] = g_ww[bo + n0 + tid];
        *(float4*)rwon_s[tid] = *(const float4*)(rwo + (bo + n0 + tid)*4);
        fwd_s[tid][0] = 0.f; fwd_s[tid][1] = 0.f; fwd_s[tid][2] = 0.f; fwd_s[tid][3] = 0.f;
    }

    float4 wwm4 = *(const float4*)(g_ww + bo + mb);
    float4 pm4  = *(const float4*)(prec + bo + mb);
    float wm[4]  = {wwm4.x, wwm4.y, wwm4.z, wwm4.w};
    float pmv[4] = {pm4.x,  pm4.y,  pm4.z,  pm4.w};
    float rwm[4][4];
    #pragma unroll
    for (int j = 0; j < 4; j++) {
        float4 t = *(const float4*)(rwo + (bo + mb + j)*4);
        rwm[j][0] = t.x; rwm[j][1] = t.y; rwm[j][2] = t.z; rwm[j][3] = t.w;
    }
    float bacc[4][4] = {};
    __syncthreads();

    const float* Lrow0 = L + (bo + n0) * (size_t)NN + mb;
    for (int i = 0; i < 128; i++) {
        const int n = n0 + i;
        const float wwn = wwn_s[i];
        const float A   = 1.0f - wwn;
        const float rn0 = rwon_s[i][0], rn1 = rwon_s[i][1];
        const float rn2 = rwon_s[i][2], rn3 = rwon_s[i][3];
        float4 Lv = __ldg((const float4*)(Lrow0 + (size_t)i * NN));
        float lv[4] = {Lv.x, Lv.y, Lv.z, Lv.w};
        float f0 = 0.f, f1 = 0.f, f2 = 0.f, f3 = 0.f;
        #pragma unroll
        for (int j = 0; j < 4; j++) {
            float a = fmaf(lv[j], A - wm[j], wwn * pmv[j]);
            if (n == mb + j) a = 0.f;                 // diag zero
            f0 = fmaf(a, rwm[j][0], f0);
            f1 = fmaf(a, rwm[j][1], f1);
            f2 = fmaf(a, rwm[j][2], f2);
            f3 = fmaf(a, rwm[j][3], f3);
            bacc[j][0] = fmaf(a, rn0, bacc[j][0]);
            bacc[j][1] = fmaf(a, rn1, bacc[j][1]);
            bacc[j][2] = fmaf(a, rn2, bacc[j][2]);
            bacc[j][3] = fmaf(a, rn3, bacc[j][3]);
        }
        #pragma unroll
        for (int o = 16; o; o >>= 1) {
            f0 += __shfl_xor_sync(0xffffffffu, f0, o);
            f1 += __shfl_xor_sync(0xffffffffu, f1, o);
            f2 += __shfl_xor_sync(0xffffffffu, f2, o);
            f3 += __shfl_xor_sync(0xffffffffu, f3, o);
        }
        if (lane < 4) {
            float fv = (lane == 0) ? f0 : (lane == 1) ? f1 : (lane == 2) ? f2 : f3;
            atomicAdd(&fwd_s[i][lane], fv);
        }
    }
    __syncthreads();

    if (tid < 128) {
        float* dst = g_fwd + (bo + n0 + tid)*4;
        atomicAdd(dst + 0, fwd_s[tid][0]);
        atomicAdd(dst + 1, fwd_s[tid][1]);
        atomicAdd(dst + 2, fwd_s[tid][2]);
        atomicAdd(dst + 3, fwd_s[tid][3]);
    }
    #pragma unroll
    for (int j = 0; j < 4; j++) {
        float* dst = g_bwd + (bo + mb + j)*4;
        atomicAdd(dst + 0, bacc[j][0]);
        atomicAdd(dst + 1, bacc[j][1]);
        atomicAdd(dst + 2, bacc[j][2]);
        atomicAdd(dst + 3, bacc[j][3]);
    }
}

// ---------------- K7: combine read modes + final bwr contraction -------------
__global__ void k7_read(const float* __restrict__ read_modes, float* __restrict__ out) {
    const int b   = blockIdx.y;
    const int n0  = blockIdx.x * 512;
    const int tid = threadIdx.x;          // 256
    const int w = tid & 63, r = tid >> 6;
    const size_t bo = (size_t)b * NN;
    __shared__ float rw_s[64][4];
    const int nl = tid >> 2, rr = tid & 3;
    const float mm0 = read_modes[b*12 + rr];       // backward mode
    const float mm1 = read_modes[b*12 + 4 + rr];   // content mode
    const float mm2 = read_modes[b*12 + 8 + rr];   // forward mode

    float acc = 0.f;
    for (int c = 0; c < 512; c += 64) {
        size_t idx = (bo + n0 + c + nl)*4 + rr;
        float rwv = mm0*g_bwd[idx] + mm1*g_cbr[idx] + mm2*g_fwd[idx];
        __syncthreads();
        rw_s[nl][rr] = rwv;
        __syncthreads();
        const float* mp = g_memnew + (bo + n0 + c)*WW + w;
        #pragma unroll 8
        for (int q = 0; q < 64; q++)
            acc = fmaf(mp[(size_t)q*WW], rw_s[q][r], acc);
    }
    atomicAdd(&out[b*WW*RR + w*RR + r], acc);
}

// ---------------- launch -----------------------------------------------------
extern "C" void kernel_launch(void* const* d_in, const int* in_sizes, int n_in,
                              void* d_out, int out_size) {
    const float* erase_vector    = (const float*)d_in[0];
    const float* free_gates      = (const float*)d_in[1];
    const float* allocation_gate = (const float*)d_in[2];
    const float* write_gate      = (const float*)d_in[3];
    const float* read_modes      = (const float*)d_in[4];
    const float* read_strengths  = (const float*)d_in[5];
    const float* read_keys       = (const float*)d_in[6];
    const float* write_vector    = (const float*)d_in[7];
    const float* write_key       = (const float*)d_in[8];
    const float* write_strength  = (const float*)d_in[9];
    const float* memory          = (const float*)d_in[10];
    const float* read_weightings = (const float*)d_in[11];
    const float* write_weighting = (const float*)d_in[12];
    const float* memory_usage    = (const float*)d_in[13];
    const float* link_matrix     = (const float*)d_in[14];
    const float* precedence      = (const float*)d_in[15];
    float* out = (float*)d_out;

    k1_usage_sim<<<dim3(16, 8), 256>>>(memory, write_key, write_strength, free_gates,
                                       read_weightings, write_weighting, memory_usage, out);
    k2_alloc<<<8, 512>>>();
    k3_ww<<<8, 1024>>>(allocation_gate, write_gate);
    k4_memupdate<<<dim3(16, 8), 256>>>(memory, erase_vector, write_vector,
                                       read_keys, read_strengths);
    k5_cbr<<<dim3(4, 8), 256>>>();
    k6_link<<<dim3(4, 32, 8), 256>>>(link_matrix, read_weightings, precedence);
    k7_read<<<dim3(8, 8), 256>>>(read_modes, out);
}

// round 3
// speedup vs baseline: 1.1834x; 1.1834x over previous
#include <cuda_runtime.h>
#include <math.h>

#define BB 8
#define NN 4096
#define WW 64
#define RR 4
#define EPSC 1e-8f

// ---------------- scratch (no allocs allowed -> __device__ globals) ----------
__device__ __align__(16) float g_usage[BB*NN];
__device__ __align__(16) float g_zw[BB*NN];
__device__ __align__(16) float g_alloc[BB*NN];
__device__ __align__(16) float g_ww[BB*NN];
__device__ __align__(16) float g_memnew[BB*NN*WW];
__device__ __align__(16) float g_zr[BB*NN*RR];
__device__ __align__(16) float g_cbr[BB*NN*RR];
__device__ __align__(16) float g_fwd[BB*NN*RR];
__device__ __align__(16) float g_bwd[BB*NN*RR];

// ---------------- K1: new usage + write content scores; zero d_out -----------
__global__ void k1_usage_sim(const float* __restrict__ memory,
                             const float* __restrict__ write_key,
                             const float* __restrict__ write_strength,
                             const float* __restrict__ free_gates,
                             const float* __restrict__ read_weightings,
                             const float* __restrict__ write_weighting,
                             const float* __restrict__ memory_usage,
                             float* __restrict__ out) {
    const int b   = blockIdx.y;
    const int tid = threadIdx.x;
    const int n   = blockIdx.x * 256 + tid;
    __shared__ float wk_s[WW];
    __shared__ float fg_s[RR];
    __shared__ float wkn;
    if (tid < WW) wk_s[tid] = write_key[b*WW + tid];
    if (tid < RR) fg_s[tid] = free_gates[b*RR + tid];
    if (blockIdx.y == 0 && blockIdx.x < 8) out[blockIdx.x*256 + tid] = 0.0f;
    __syncthreads();
    if (tid == 0) {
        float s = 0.f;
        for (int w = 0; w < WW; w++) s += wk_s[w]*wk_s[w];
        wkn = sqrtf(s);
    }
    __syncthreads();

    const size_t bn = (size_t)b*NN + n;
    float u  = memory_usage[bn];
    float wv = write_weighting[bn];
    float uw = u + wv - u*wv;
    float4 rw = *(const float4*)(read_weightings + bn*RR);
    float prod = (1.f - rw.x*fg_s[0]) * (1.f - rw.y*fg_s[1])
               * (1.f - rw.z*fg_s[2]) * (1.f - rw.w*fg_s[3]);
    g_usage[bn] = uw * prod;

    const float4* mrow = (const float4*)(memory + bn*WW);
    float dot = 0.f, nrm = 0.f;
    #pragma unroll
    for (int i = 0; i < 16; i++) {
        float4 m = mrow[i];
        dot += m.x*wk_s[i*4+0] + m.y*wk_s[i*4+1] + m.z*wk_s[i*4+2] + m.w*wk_s[i*4+3];
        nrm += m.x*m.x + m.y*m.y + m.z*m.z + m.w*m.w;
    }
    float sim = dot / (wkn * sqrtf(nrm) + EPSC);
    g_zw[bn] = write_strength[b] * sim;
}

// ---------------- K2: per-batch sort -> allocation weights -------------------
__global__ void k2_alloc() {
    const int b   = blockIdx.x;
    const int tid = threadIdx.x;  // 512 threads
    __shared__ float sv[NN];
    __shared__ int   si[NN];
    __shared__ float cp[512];

    for (int i = tid; i < NN; i += 512) { sv[i] = g_usage[(size_t)b*NN + i]; si[i] = i; }
    __syncthreads();

    // bitonic sort ascending (matches jnp.argsort)
    for (int k = 2; k <= NN; k <<= 1) {
        for (int j = k >> 1; j > 0; j >>= 1) {
            for (int i = tid; i < NN; i += 512) {
                int ixj = i ^ j;
                if (ixj > i) {
                    bool up = ((i & k) == 0);
                    float a = sv[i], c = sv[ixj];
                    bool sw = up ? (a > c) : (a < c);
                    if (sw) {
                        sv[i] = c; sv[ixj] = a;
                        int t = si[i]; si[i] = si[ixj]; si[ixj] = t;
                    }
                }
            }
            __syncthreads();
        }
    }

    // chunked exclusive prefix product of sorted usage
    float p = 1.f;
    const int base = tid * 8;
    #pragma unroll
    for (int t = 0; t < 8; t++) p *= sv[base + t];
    cp[tid] = p;
    __syncthreads();
    for (int off = 1; off < 512; off <<= 1) {
        float v = cp[tid];
        float o = (tid >= off) ? cp[tid - off] : 1.f;
        __syncthreads();
        cp[tid] = v * o;
        __syncthreads();
    }
    float run = (tid == 0) ? 1.f : cp[tid - 1];
    #pragma unroll
    for (int t = 0; t < 8; t++) {
        float v = sv[base + t];
        g_alloc[(size_t)b*NN + si[base + t]] = (1.f - v) * run;
        run *= v;
    }
}

// ---------------- K3: softmax(cbw) + final write weighting -------------------
__global__ void k3_ww(const float* __restrict__ allocation_gate,
                      const float* __restrict__ write_gate) {
    const int b   = blockIdx.x;
    const int tid = threadIdx.x;  // 1024
    __shared__ float sh[32];
    const size_t bo = (size_t)b*NN;

    float z[4];
    float lm = -3.4e38f;
    #pragma unroll
    for (int k = 0; k < 4; k++) { z[k] = g_zw[bo + tid + k*1024]; lm = fmaxf(lm, z[k]); }
    for (int o = 16; o; o >>= 1) lm = fmaxf(lm, __shfl_xor_sync(0xffffffffu, lm, o));
    if ((tid & 31) == 0) sh[tid >> 5] = lm;
    __syncthreads();
    if (tid < 32) {
        float v = sh[tid];
        for (int o = 16; o; o >>= 1) v = fmaxf(v, __shfl_xor_sync(0xffffffffu, v, o));
        if (tid == 0) sh[0] = v;
    }
    __syncthreads();
    const float bmax = sh[0];
    __syncthreads();

    float e[4], ls = 0.f;
    #pragma unroll
    for (int k = 0; k < 4; k++) { e[k] = expf(z[k] - bmax); ls += e[k]; }
    for (int o = 16; o; o >>= 1) ls += __shfl_xor_sync(0xffffffffu, ls, o);
    if ((tid & 31) == 0) sh[tid >> 5] = ls;
    __syncthreads();
    if (tid < 32) {
        float v = sh[tid];
        for (int o = 16; o; o >>= 1) v += __shfl_xor_sync(0xffffffffu, v, o);
        if (tid == 0) sh[0] = v;
    }
    __syncthreads();
    const float bsum = sh[0];

    const float ag = allocation_gate[b], wg = write_gate[b];
    #pragma unroll
    for (int k = 0; k < 4; k++) {
        size_t idx = bo + tid + k*1024;
        float cbw = e[k] / bsum;
        g_ww[idx] = wg * (ag * g_alloc[idx] + (1.f - ag) * cbw);
    }
}

// ---------------- K4: memory erase/write + read content scores --------------
__global__ void k4_memupdate(const float* __restrict__ memory,
                             const float* __restrict__ erase_vector,
                             const float* __restrict__ write_vector,
                             const float* __restrict__ read_keys,
                             const float* __restrict__ read_strengths) {
    const int b   = blockIdx.y;
    const int tid = threadIdx.x;
    const int n   = blockIdx.x * 256 + tid;
    __shared__ float rk_s[WW][RR];
    __shared__ float ev_s[WW], wv_s[WW];
    __shared__ float nrk_s[RR], rs_s[RR];

    if (tid < WW) { ev_s[tid] = erase_vector[b*WW + tid]; wv_s[tid] = write_vector[b*WW + tid]; }
    { int w = tid >> 2, r = tid & 3; rk_s[w][r] = read_keys[b*WW*RR + tid]; }
    __syncthreads();
    if (tid < RR) {
        float s = 0.f;
        for (int w = 0; w < WW; w++) { float v = rk_s[w][tid]; s += v*v; }
        nrk_s[tid] = sqrtf(s);
        rs_s[tid]  = read_strengths[b*RR + tid];
    }
    __syncthreads();

    const size_t bn = (size_t)b*NN + n;
    const float wwn = g_ww[bn];
    const float4* mrow = (const float4*)(memory + bn*WW);
    float4* orow = (float4*)(g_memnew + bn*WW);

    float nrm = 0.f, s0 = 0.f, s1 = 0.f, s2 = 0.f, s3 = 0.f;
    #pragma unroll
    for (int i = 0; i < 16; i++) {
        float4 m = mrow[i];
        float mv[4] = {m.x, m.y, m.z, m.w};
        float ov[4];
        #pragma unroll
        for (int c = 0; c < 4; c++) {
            int w = i*4 + c;
            ov[c] = fmaf(mv[c], 1.f - wwn*ev_s[w], wwn*wv_s[w]);
            nrm += ov[c]*ov[c];
            s0 = fmaf(ov[c], rk_s[w][0], s0);
            s1 = fmaf(ov[c], rk_s[w][1], s1);
            s2 = fmaf(ov[c], rk_s[w][2], s2);
            s3 = fmaf(ov[c], rk_s[w][3], s3);
        }
        float4 o4 = make_float4(ov[0], ov[1], ov[2], ov[3]);
        orow[i] = o4;
    }
    const float nn = sqrtf(nrm);
    float4 zr;
    zr.x = rs_s[0]*s0 / (nn*nrk_s[0] + EPSC);
    zr.y = rs_s[1]*s1 / (nn*nrk_s[1] + EPSC);
    zr.z = rs_s[2]*s2 / (nn*nrk_s[2] + EPSC);
    zr.w = rs_s[3]*s3 / (nn*nrk_s[3] + EPSC);
    *(float4*)(g_zr + bn*RR) = zr;
}

// ---------------- K5: softmax(cbr) per (b,r); zeroes fwd/bwd -----------------
__global__ void k5_cbr() {
    const int r = blockIdx.x, b = blockIdx.y;
    const int tid = threadIdx.x;  // 256
    __shared__ float sh[8];
    const size_t bo = (size_t)b*NN;

    float z[16];
    float lm = -3.4e38f;
    #pragma unroll
    for (int k = 0; k < 16; k++) {
        size_t idx = (bo + tid + (size_t)k*256)*RR + r;
        z[k] = g_zr[idx];
        g_fwd[idx] = 0.f;
        g_bwd[idx] = 0.f;
        lm = fmaxf(lm, z[k]);
    }
    for (int o = 16; o; o >>= 1) lm = fmaxf(lm, __shfl_xor_sync(0xffffffffu, lm, o));
    if ((tid & 31) == 0) sh[tid >> 5] = lm;
    __syncthreads();
    if (tid < 8) {
        float v = sh[tid];
        for (int o = 4; o; o >>= 1) v = fmaxf(v, __shfl_xor_sync(0xffu, v, o));
        if (tid == 0) sh[0] = v;
    }
    __syncthreads();
    const float bmax = sh[0];
    __syncthreads();

    float ls = 0.f;
    #pragma unroll
    for (int k = 0; k < 16; k++) { z[k] = expf(z[k] - bmax); ls += z[k]; }
    for (int o = 16; o; o >>= 1) ls += __shfl_xor_sync(0xffffffffu, ls, o);
    if ((tid & 31) == 0) sh[tid >> 5] = ls;
    __syncthreads();
    if (tid < 8) {
        float v = sh[tid];
        for (int o = 4; o; o >>= 1) v += __shfl_xor_sync(0xffu, v, o);
        if (tid == 0) sh[0] = v;
    }
    __syncthreads();
    const float bsum = sh[0];

    #pragma unroll
    for (int k = 0; k < 16; k++) {
        size_t idx = (bo + tid + (size_t)k*256)*RR + r;
        g_cbr[idx] = z[k] / bsum;
    }
}

// ---------------- K6: fused link update + fwd/bwd (smem tile, no shuffles) ---
// a[n][m] = (1-ww_n-ww_m)*L[n][m] + ww_n*p_m, diag zeroed (never materialized)
// fwd[n,r] += a[n][m]*rwo[m,r]   ;   bwd[m,r] += a[n][m]*rwo[n,r]
#define TN 64
#define TM 128
#define TPAD 133
__global__ void __launch_bounds__(256) k6_link(const float* __restrict__ L,
                        const float* __restrict__ rwo,
                        const float* __restrict__ prec) {
    const int b   = blockIdx.z;
    const int n0  = blockIdx.y * TN;
    const int m0  = blockIdx.x * TM;
    const int tid = threadIdx.x;     // 256
    const size_t bo = (size_t)b * NN;

    __shared__ float a_s[TN][TPAD];
    __shared__ float wwn_s[TN];
    __shared__ __align__(16) float4 rn_s[TN];
    __shared__ __align__(16) float4 rm_s[TM];
    __shared__ float fp_s[4][TN][4];
    __shared__ float bp_s[TM][4];

    // ---- issue all L loads first (MLP=8, hides prefill + DRAM latency) ----
    const int lrow0 = tid >> 5;          // 0..7 (warp id = row)
    const int lc4   = (tid & 31) * 4;    // column quad within tile
    float4 lv[8];
    const float* Lbase = L + (bo + n0 + lrow0) * (size_t)NN + m0 + lc4;
    #pragma unroll
    for (int k = 0; k < 8; k++)
        lv[k] = __ldg((const float4*)(Lbase + (size_t)(k * 8) * NN));

    // ---- prefill small smem ----
    if (tid < TN) {
        wwn_s[tid] = g_ww[bo + n0 + tid];
        rn_s[tid]  = *(const float4*)(rwo + (bo + n0 + tid)*4);
    }
    if (tid < TM) {
        rm_s[tid] = *(const float4*)(rwo + (bo + m0 + tid)*4);
        bp_s[tid][0] = 0.f; bp_s[tid][1] = 0.f; bp_s[tid][2] = 0.f; bp_s[tid][3] = 0.f;
    }
    const float4 wm4 = *(const float4*)(g_ww + bo + m0 + lc4);
    const float4 pm4 = *(const float4*)(prec + bo + m0 + lc4);
    __syncthreads();

    // ---- compute a tile into smem ----
    #pragma unroll
    for (int k = 0; k < 8; k++) {
        const int row = lrow0 + k * 8;
        const int n   = n0 + row;
        const float wwn = wwn_s[row];
        const float A   = 1.0f - wwn;
        float a0 = fmaf(lv[k].x, A - wm4.x, wwn * pm4.x);
        float a1 = fmaf(lv[k].y, A - wm4.y, wwn * pm4.y);
        float a2 = fmaf(lv[k].z, A - wm4.z, wwn * pm4.z);
        float a3 = fmaf(lv[k].w, A - wm4.w, wwn * pm4.w);
        if (n == m0 + lc4 + 0) a0 = 0.f;
        if (n == m0 + lc4 + 1) a1 = 0.f;
        if (n == m0 + lc4 + 2) a2 = 0.f;
        if (n == m0 + lc4 + 3) a3 = 0.f;
        a_s[row][lc4+0] = a0; a_s[row][lc4+1] = a1;
        a_s[row][lc4+2] = a2; a_s[row][lc4+3] = a3;
    }
    __syncthreads();

    // ---- fwd pass: thread owns (row, col-quarter), lane-private accum ----
    {
        const int row = tid & 63;
        const int q   = tid >> 6;
        float f0 = 0.f, f1 = 0.f, f2 = 0.f, f3 = 0.f;
        #pragma unroll
        for (int c0 = 0; c0 < 32; c0++) {
            const int c = q * 32 + c0;
            const float a  = a_s[row][c];
            const float4 rm = rm_s[c];
            f0 = fmaf(a, rm.x, f0);
            f1 = fmaf(a, rm.y, f1);
            f2 = fmaf(a, rm.z, f2);
            f3 = fmaf(a, rm.w, f3);
        }
        fp_s[q][row][0] = f0; fp_s[q][row][1] = f1;
        fp_s[q][row][2] = f2; fp_s[q][row][3] = f3;
    }

    // ---- bwd pass: thread owns (col, row-half), lane-private accum ----
    {
        const int col  = tid & 127;
        const int half = tid >> 7;
        float b0 = 0.f, b1 = 0.f, b2 = 0.f, b3 = 0.f;
        #pragma unroll
        for (int i0 = 0; i0 < 32; i0++) {
            const int n = half * 32 + i0;
            const float a  = a_s[n][col];
            const float4 rn = rn_s[n];
            b0 = fmaf(a, rn.x, b0);
            b1 = fmaf(a, rn.y, b1);
            b2 = fmaf(a, rn.z, b2);
            b3 = fmaf(a, rn.w, b3);
        }
        atomicAdd(&bp_s[col][0], b0);
        atomicAdd(&bp_s[col][1], b1);
        atomicAdd(&bp_s[col][2], b2);
        atomicAdd(&bp_s[col][3], b3);
    }
    __syncthreads();

    // ---- global reductions ----
    {
        const int row = tid >> 2, rr = tid & 3;
        const float s = fp_s[0][row][rr] + fp_s[1][row][rr]
                      + fp_s[2][row][rr] + fp_s[3][row][rr];
        atomicAdd(g_fwd + (bo + n0 + row)*4 + rr, s);
    }
    if (tid < TM) {
        float* dst = g_bwd + (bo + m0 + tid)*4;
        atomicAdd(dst + 0, bp_s[tid][0]);
        atomicAdd(dst + 1, bp_s[tid][1]);
        atomicAdd(dst + 2, bp_s[tid][2]);
        atomicAdd(dst + 3, bp_s[tid][3]);
    }
}

// ---------------- K7: combine read modes + final bwr contraction -------------
__global__ void k7_read(const float* __restrict__ read_modes, float* __restrict__ out) {
    const int b   = blockIdx.y;
    const int n0  = blockIdx.x * 512;
    const int tid = threadIdx.x;          // 256
    const int w = tid & 63, r = tid >> 6;
    const size_t bo = (size_t)b * NN;
    __shared__ float rw_s[64][4];
    const int nl = tid >> 2, rr = tid & 3;
    const float mm0 = read_modes[b*12 + rr];       // backward mode
    const float mm1 = read_modes[b*12 + 4 + rr];   // content mode
    const float mm2 = read_modes[b*12 + 8 + rr];   // forward mode

    float acc = 0.f;
    for (int c = 0; c < 512; c += 64) {
        size_t idx = (bo + n0 + c + nl)*4 + rr;
        float rwv = mm0*g_bwd[idx] + mm1*g_cbr[idx] + mm2*g_fwd[idx];
        __syncthreads();
        rw_s[nl][rr] = rwv;
        __syncthreads();
        const float* mp = g_memnew + (bo + n0 + c)*WW + w;
        #pragma unroll 8
        for (int q = 0; q < 64; q++)
            acc = fmaf(mp[(size_t)q*WW], rw_s[q][r], acc);
    }
    atomicAdd(&out[b*WW*RR + w*RR + r], acc);
}

// ---------------- launch -----------------------------------------------------
extern "C" void kernel_launch(void* const* d_in, const int* in_sizes, int n_in,
                              void* d_out, int out_size) {
    const float* erase_vector    = (const float*)d_in[0];
    const float* free_gates      = (const float*)d_in[1];
    const float* allocation_gate = (const float*)d_in[2];
    const float* write_gate      = (const float*)d_in[3];
    const float* read_modes      = (const float*)d_in[4];
    const float* read_strengths  = (const float*)d_in[5];
    const float* read_keys       = (const float*)d_in[6];
    const float* write_vector    = (const float*)d_in[7];
    const float* write_key       = (const float*)d_in[8];
    const float* write_strength  = (const float*)d_in[9];
    const float* memory          = (const float*)d_in[10];
    const float* read_weightings = (const float*)d_in[11];
    const float* write_weighting = (const float*)d_in[12];
    const float* memory_usage    = (const float*)d_in[13];
    const float* link_matrix     = (const float*)d_in[14];
    const float* precedence      = (const float*)d_in[15];
    float* out = (float*)d_out;

    k1_usage_sim<<<dim3(16, 8), 256>>>(memory, write_key, write_strength, free_gates,
                                       read_weightings, write_weighting, memory_usage, out);
    k2_alloc<<<8, 512>>>();
    k3_ww<<<8, 1024>>>(allocation_gate, write_gate);
    k4_memupdate<<<dim3(16, 8), 256>>>(memory, erase_vector, write_vector,
                                       read_keys, read_strengths);
    k5_cbr<<<dim3(4, 8), 256>>>();
    k6_link<<<dim3(NN/TM, NN/TN, BB), 256>>>(link_matrix, read_weightings, precedence);
    k7_read<<<dim3(8, 8), 256>>>(read_modes, out);
}

// round 4
// speedup vs baseline: 1.1968x; 1.0113x over previous
#include <cuda_runtime.h>
#include <math.h>

#define BB 8
#define NN 4096
#define WW 64
#define RR 4
#define EPSC 1e-8f

// ---------------- scratch (no allocs allowed -> __device__ globals) ----------
__device__ __align__(16) float g_usage[BB*NN];
__device__ __align__(16) float g_zw[BB*NN];
__device__ __align__(16) float g_alloc[BB*NN];
__device__ __align__(16) float g_ww[BB*NN];
__device__ __align__(16) float g_memnew[BB*NN*WW];
__device__ __align__(16) float g_zr[BB*NN*RR];
__device__ __align__(16) float g_cbr[BB*NN*RR];
__device__ __align__(16) float g_fwd[BB*NN*RR];
__device__ __align__(16) float g_bwd[BB*NN*RR];

// ---------------- K1: new usage + write content scores; zero d_out -----------
__global__ void k1_usage_sim(const float* __restrict__ memory,
                             const float* __restrict__ write_key,
                             const float* __restrict__ write_strength,
                             const float* __restrict__ free_gates,
                             const float* __restrict__ read_weightings,
                             const float* __restrict__ write_weighting,
                             const float* __restrict__ memory_usage,
                             float* __restrict__ out) {
    const int b   = blockIdx.y;
    const int tid = threadIdx.x;
    const int n   = blockIdx.x * 256 + tid;
    __shared__ float wk_s[WW];
    __shared__ float fg_s[RR];
    __shared__ float wkn;
    if (tid < WW) wk_s[tid] = write_key[b*WW + tid];
    if (tid < RR) fg_s[tid] = free_gates[b*RR + tid];
    if (blockIdx.y == 0 && blockIdx.x < 8) out[blockIdx.x*256 + tid] = 0.0f;
    __syncthreads();
    if (tid == 0) {
        float s = 0.f;
        for (int w = 0; w < WW; w++) s += wk_s[w]*wk_s[w];
        wkn = sqrtf(s);
    }
    __syncthreads();

    const size_t bn = (size_t)b*NN + n;
    float u  = memory_usage[bn];
    float wv = write_weighting[bn];
    float uw = u + wv - u*wv;
    float4 rw = *(const float4*)(read_weightings + bn*RR);
    float prod = (1.f - rw.x*fg_s[0]) * (1.f - rw.y*fg_s[1])
               * (1.f - rw.z*fg_s[2]) * (1.f - rw.w*fg_s[3]);
    g_usage[bn] = uw * prod;

    const float4* mrow = (const float4*)(memory + bn*WW);
    float dot = 0.f, nrm = 0.f;
    #pragma unroll
    for (int i = 0; i < 16; i++) {
        float4 m = mrow[i];
        dot += m.x*wk_s[i*4+0] + m.y*wk_s[i*4+1] + m.z*wk_s[i*4+2] + m.w*wk_s[i*4+3];
        nrm += m.x*m.x + m.y*m.y + m.z*m.z + m.w*m.w;
    }
    float sim = dot / (wkn * sqrtf(nrm) + EPSC);
    g_zw[bn] = write_strength[b] * sim;
}

// ---------------- K2: per-batch sort -> allocation weights -------------------
__global__ void k2_alloc() {
    const int b   = blockIdx.x;
    const int tid = threadIdx.x;  // 512 threads
    __shared__ float sv[NN];
    __shared__ int   si[NN];
    __shared__ float cp[512];

    for (int i = tid; i < NN; i += 512) { sv[i] = g_usage[(size_t)b*NN + i]; si[i] = i; }
    __syncthreads();

    for (int k = 2; k <= NN; k <<= 1) {
        for (int j = k >> 1; j > 0; j >>= 1) {
            for (int i = tid; i < NN; i += 512) {
                int ixj = i ^ j;
                if (ixj > i) {
                    bool up = ((i & k) == 0);
                    float a = sv[i], c = sv[ixj];
                    bool sw = up ? (a > c) : (a < c);
                    if (sw) {
                        sv[i] = c; sv[ixj] = a;
                        int t = si[i]; si[i] = si[ixj]; si[ixj] = t;
                    }
                }
            }
            __syncthreads();
        }
    }

    float p = 1.f;
    const int base = tid * 8;
    #pragma unroll
    for (int t = 0; t < 8; t++) p *= sv[base + t];
    cp[tid] = p;
    __syncthreads();
    for (int off = 1; off < 512; off <<= 1) {
        float v = cp[tid];
        float o = (tid >= off) ? cp[tid - off] : 1.f;
        __syncthreads();
        cp[tid] = v * o;
        __syncthreads();
    }
    float run = (tid == 0) ? 1.f : cp[tid - 1];
    #pragma unroll
    for (int t = 0; t < 8; t++) {
        float v = sv[base + t];
        g_alloc[(size_t)b*NN + si[base + t]] = (1.f - v) * run;
        run *= v;
    }
}

// ---------------- K3: softmax(cbw) + final ww; also zero g_fwd/g_bwd ---------
__global__ void k3_ww(const float* __restrict__ allocation_gate,
                      const float* __restrict__ write_gate) {
    const int b   = blockIdx.x;
    const int tid = threadIdx.x;  // 1024
    __shared__ float sh[32];
    const size_t bo = (size_t)b*NN;

    // zero fwd/bwd accumulators for this batch (needed every graph replay)
    {
        float4 z4 = make_float4(0.f, 0.f, 0.f, 0.f);
        float4* f4 = (float4*)(g_fwd + bo*RR);
        float4* b4 = (float4*)(g_bwd + bo*RR);
        #pragma unroll
        for (int i = 0; i < 4; i++) { f4[tid + i*1024] = z4; b4[tid + i*1024] = z4; }
    }

    float z[4];
    float lm = -3.4e38f;
    #pragma unroll
    for (int k = 0; k < 4; k++) { z[k] = g_zw[bo + tid + k*1024]; lm = fmaxf(lm, z[k]); }
    for (int o = 16; o; o >>= 1) lm = fmaxf(lm, __shfl_xor_sync(0xffffffffu, lm, o));
    if ((tid & 31) == 0) sh[tid >> 5] = lm;
    __syncthreads();
    if (tid < 32) {
        float v = sh[tid];
        for (int o = 16; o; o >>= 1) v = fmaxf(v, __shfl_xor_sync(0xffffffffu, v, o));
        if (tid == 0) sh[0] = v;
    }
    __syncthreads();
    const float bmax = sh[0];
    __syncthreads();

    float e[4], ls = 0.f;
    #pragma unroll
    for (int k = 0; k < 4; k++) { e[k] = expf(z[k] - bmax); ls += e[k]; }
    for (int o = 16; o; o >>= 1) ls += __shfl_xor_sync(0xffffffffu, ls, o);
    if ((tid & 31) == 0) sh[tid >> 5] = ls;
    __syncthreads();
    if (tid < 32) {
        float v = sh[tid];
        for (int o = 16; o; o >>= 1) v += __shfl_xor_sync(0xffffffffu, v, o);
        if (tid == 0) sh[0] = v;
    }
    __syncthreads();
    const float bsum = sh[0];

    const float ag = allocation_gate[b], wg = write_gate[b];
    #pragma unroll
    for (int k = 0; k < 4; k++) {
        size_t idx = bo + tid + k*1024;
        float cbw = e[k] / bsum;
        g_ww[idx] = wg * (ag * g_alloc[idx] + (1.f - ag) * cbw);
    }
}

// ---------------- K4: memory erase/write + read content scores --------------
__global__ void k4_memupdate(const float* __restrict__ memory,
                             const float* __restrict__ erase_vector,
                             const float* __restrict__ write_vector,
                             const float* __restrict__ read_keys,
                             const float* __restrict__ read_strengths) {
    const int b   = blockIdx.y;
    const int tid = threadIdx.x;
    const int n   = blockIdx.x * 256 + tid;
    __shared__ float rk_s[WW][RR];
    __shared__ float ev_s[WW], wv_s[WW];
    __shared__ float nrk_s[RR], rs_s[RR];

    if (tid < WW) { ev_s[tid] = erase_vector[b*WW + tid]; wv_s[tid] = write_vector[b*WW + tid]; }
    { int w = tid >> 2, r = tid & 3; rk_s[w][r] = read_keys[b*WW*RR + tid]; }
    __syncthreads();
    if (tid < RR) {
        float s = 0.f;
        for (int w = 0; w < WW; w++) { float v = rk_s[w][tid]; s += v*v; }
        nrk_s[tid] = sqrtf(s);
        rs_s[tid]  = read_strengths[b*RR + tid];
    }
    __syncthreads();

    const size_t bn = (size_t)b*NN + n;
    const float wwn = g_ww[bn];
    const float4* mrow = (const float4*)(memory + bn*WW);
    float4* orow = (float4*)(g_memnew + bn*WW);

    float nrm = 0.f, s0 = 0.f, s1 = 0.f, s2 = 0.f, s3 = 0.f;
    #pragma unroll
    for (int i = 0; i < 16; i++) {
        float4 m = mrow[i];
        float mv[4] = {m.x, m.y, m.z, m.w};
        float ov[4];
        #pragma unroll
        for (int c = 0; c < 4; c++) {
            int w = i*4 + c;
            ov[c] = fmaf(mv[c], 1.f - wwn*ev_s[w], wwn*wv_s[w]);
            nrm += ov[c]*ov[c];
            s0 = fmaf(ov[c], rk_s[w][0], s0);
            s1 = fmaf(ov[c], rk_s[w][1], s1);
            s2 = fmaf(ov[c], rk_s[w][2], s2);
            s3 = fmaf(ov[c], rk_s[w][3], s3);
        }
        float4 o4 = make_float4(ov[0], ov[1], ov[2], ov[3]);
        orow[i] = o4;
    }
    const float nn = sqrtf(nrm);
    float4 zr;
    zr.x = rs_s[0]*s0 / (nn*nrk_s[0] + EPSC);
    zr.y = rs_s[1]*s1 / (nn*nrk_s[1] + EPSC);
    zr.z = rs_s[2]*s2 / (nn*nrk_s[2] + EPSC);
    zr.w = rs_s[3]*s3 / (nn*nrk_s[3] + EPSC);
    *(float4*)(g_zr + bn*RR) = zr;
}

// ---------------- K5: softmax(cbr) per (b,r) ---------------------------------
__global__ void k5_cbr() {
    const int r = blockIdx.x, b = blockIdx.y;
    const int tid = threadIdx.x;  // 256
    __shared__ float sh[8];
    const size_t bo = (size_t)b*NN;

    float z[16];
    float lm = -3.4e38f;
    #pragma unroll
    for (int k = 0; k < 16; k++) {
        size_t idx = (bo + tid + (size_t)k*256)*RR + r;
        z[k] = g_zr[idx];
        lm = fmaxf(lm, z[k]);
    }
    for (int o = 16; o; o >>= 1) lm = fmaxf(lm, __shfl_xor_sync(0xffffffffu, lm, o));
    if ((tid & 31) == 0) sh[tid >> 5] = lm;
    __syncthreads();
    if (tid < 8) {
        float v = sh[tid];
        for (int o = 4; o; o >>= 1) v = fmaxf(v, __shfl_xor_sync(0xffu, v, o));
        if (tid == 0) sh[0] = v;
    }
    __syncthreads();
    const float bmax = sh[0];
    __syncthreads();

    float ls = 0.f;
    #pragma unroll
    for (int k = 0; k < 16; k++) { z[k] = expf(z[k] - bmax); ls += z[k]; }
    for (int o = 16; o; o >>= 1) ls += __shfl_xor_sync(0xffffffffu, ls, o);
    if ((tid & 31) == 0) sh[tid >> 5] = ls;
    __syncthreads();
    if (tid < 8) {
        float v = sh[tid];
        for (int o = 4; o; o >>= 1) v += __shfl_xor_sync(0xffu, v, o);
        if (tid == 0) sh[0] = v;
    }
    __syncthreads();
    const float bsum = sh[0];

    #pragma unroll
    for (int k = 0; k < 16; k++) {
        size_t idx = (bo + tid + (size_t)k*256)*RR + r;
        g_cbr[idx] = z[k] / bsum;
    }
}

// ---------------- K6 v3: register-blocked fused link update + fwd/bwd --------
// a[n][m] = (1-ww_n-ww_m)*L[n][m] + ww_n*p_m, diag zeroed (never materialized)
// fwd[n,r] += a[n][m]*rwo[m,r]   ;   bwd[m,r] += a[n][m]*rwo[n,r]
// Thread patch: 8 rows x 4 cols per chunk. bwd accumulates 256 rows in regs.
// fwd reduced per chunk by warp reduce-scatter butterfly (31 SHFL / 32 elems).
#define K6_TM  128    // cols per block (32 lanes x 4)
#define K6_CH  64     // rows per chunk (8 warps x 8)
#define K6_NCH 4      // chunks -> 256 rows per block
__global__ void __launch_bounds__(256, 2) k6_link(const float* __restrict__ L,
                        const float* __restrict__ rwo,
                        const float* __restrict__ prec) {
    const int b    = blockIdx.z;
    const int m0   = blockIdx.x * K6_TM;
    const int n00  = blockIdx.y * (K6_CH * K6_NCH);
    const int tid  = threadIdx.x;     // 256
    const int warp = tid >> 5, lane = tid & 31;
    const size_t bo = (size_t)b * NN;
    const int mc   = m0 + lane * 4;   // this thread's 4 columns

    __shared__ float wwn_s[K6_CH];
    __shared__ __align__(16) float4 rn_s[K6_CH];
    __shared__ float bp_s[K6_TM][4];

    // per-thread column constants (held in regs for all 256 rows)
    const float4 wm4 = __ldg((const float4*)(g_ww + bo + mc));
    const float4 pm4 = __ldg((const float4*)(prec + bo + mc));
    float wm[4] = {wm4.x, wm4.y, wm4.z, wm4.w};
    float pm[4] = {pm4.x, pm4.y, pm4.z, pm4.w};
    float4 rm[4];
    #pragma unroll
    for (int c = 0; c < 4; c++) rm[c] = __ldg((const float4*)(rwo + (size_t)(bo + mc + c)*4));

    if (tid < K6_TM) { bp_s[tid][0]=0.f; bp_s[tid][1]=0.f; bp_s[tid][2]=0.f; bp_s[tid][3]=0.f; }

    float bacc[4][4] = {};   // bwd partials for this thread's 4 cols, all 256 rows

    for (int ch = 0; ch < K6_NCH; ch++) {
        const int n0 = n00 + ch * K6_CH;
        __syncthreads();
        if (tid < K6_CH) {
            wwn_s[tid] = g_ww[bo + n0 + tid];
            rn_s[tid]  = *(const float4*)(rwo + (size_t)(bo + n0 + tid)*4);
        }
        __syncthreads();

        const int rb = warp * 8;   // warp's 8 rows within chunk
        // issue all 8 row loads up front (MLP=8, 512B/warp coalesced)
        float4 lv[8];
        const float* Lb = L + (bo + n0 + rb) * (size_t)NN + mc;
        #pragma unroll
        for (int k = 0; k < 8; k++)
            lv[k] = __ldg((const float4*)(Lb + (size_t)k * NN));

        const bool hd = (m0 < n0 + K6_CH) && (n0 < m0 + K6_TM);  // diag in range?
        float v[32];   // fwd partials: v[row*4 + r]

        #pragma unroll
        for (int k = 0; k < 8; k++) {
            const int n   = n0 + rb + k;
            const float wwn = wwn_s[rb + k];
            const float A   = 1.f - wwn;
            const float4 rn = rn_s[rb + k];
            float a[4];
            a[0] = fmaf(lv[k].x, A - wm[0], wwn * pm[0]);
            a[1] = fmaf(lv[k].y, A - wm[1], wwn * pm[1]);
            a[2] = fmaf(lv[k].z, A - wm[2], wwn * pm[2]);
            a[3] = fmaf(lv[k].w, A - wm[3], wwn * pm[3]);
            if (hd) {
                if (n == mc + 0) a[0] = 0.f;
                if (n == mc + 1) a[1] = 0.f;
                if (n == mc + 2) a[2] = 0.f;
                if (n == mc + 3) a[3] = 0.f;
            }
            // bwd: accumulate over rows (stays in regs across whole block)
            #pragma unroll
            for (int c = 0; c < 4; c++) {
                bacc[c][0] = fmaf(a[c], rn.x, bacc[c][0]);
                bacc[c][1] = fmaf(a[c], rn.y, bacc[c][1]);
                bacc[c][2] = fmaf(a[c], rn.z, bacc[c][2]);
                bacc[c][3] = fmaf(a[c], rn.w, bacc[c][3]);
            }
            // fwd partial over this thread's 4 cols
            v[k*4+0] = fmaf(a[3], rm[3].x, fmaf(a[2], rm[2].x, fmaf(a[1], rm[1].x, a[0]*rm[0].x)));
            v[k*4+1] = fmaf(a[3], rm[3].y, fmaf(a[2], rm[2].y, fmaf(a[1], rm[1].y, a[0]*rm[0].y)));
            v[k*4+2] = fmaf(a[3], rm[3].z, fmaf(a[2], rm[2].z, fmaf(a[1], rm[1].z, a[0]*rm[0].z)));
            v[k*4+3] = fmaf(a[3], rm[3].w, fmaf(a[2], rm[2].w, fmaf(a[1], rm[1].w, a[0]*rm[0].w)));
        }

        // reduce-scatter butterfly across 32 lanes: lane ends with full sum of v[lane]
        #pragma unroll
        for (int h = 16; h >= 1; h >>= 1) {
            const bool up = (lane & h) != 0;
            #pragma unroll
            for (int i = 0; i < h; i++) {
                float send = up ? v[i] : v[i+h];
                float recv = __shfl_xor_sync(0xffffffffu, send, h);
                v[i] = (up ? v[i+h] : v[i]) + recv;
            }
        }
        // lane holds fwd sum for (row = rb + lane/4, r = lane%4) over 128 cols
        atomicAdd(g_fwd + (size_t)(bo + n0 + rb + (lane >> 2))*4 + (lane & 3), v[0]);
    }

    // merge bwd partials: 8-warp contention, spread addresses within warp
    __syncthreads();
    #pragma unroll
    for (int c = 0; c < 4; c++) {
        float* dst = bp_s[lane*4 + c];
        atomicAdd(dst + 0, bacc[c][0]);
        atomicAdd(dst + 1, bacc[c][1]);
        atomicAdd(dst + 2, bacc[c][2]);
        atomicAdd(dst + 3, bacc[c][3]);
    }
    __syncthreads();
    if (tid < K6_TM) {
        float* dst = g_bwd + (size_t)(bo + m0 + tid)*4;
        atomicAdd(dst + 0, bp_s[tid][0]);
        atomicAdd(dst + 1, bp_s[tid][1]);
        atomicAdd(dst + 2, bp_s[tid][2]);
        atomicAdd(dst + 3, bp_s[tid][3]);
    }
}

// ---------------- K7: combine read modes + final bwr contraction -------------
__global__ void k7_read(const float* __restrict__ read_modes, float* __restrict__ out) {
    const int b   = blockIdx.y;
    const int n0  = blockIdx.x * 512;
    const int tid = threadIdx.x;          // 256
    const int w = tid & 63, r = tid >> 6;
    const size_t bo = (size_t)b * NN;
    __shared__ float rw_s[64][4];
    const int nl = tid >> 2, rr = tid & 3;
    const float mm0 = read_modes[b*12 + rr];
    const float mm1 = read_modes[b*12 + 4 + rr];
    const float mm2 = read_modes[b*12 + 8 + rr];

    float acc = 0.f;
    for (int c = 0; c < 512; c += 64) {
        size_t idx = (bo + n0 + c + nl)*4 + rr;
        float rwv = mm0*g_bwd[idx] + mm1*g_cbr[idx] + mm2*g_fwd[idx];
        __syncthreads();
        rw_s[nl][rr] = rwv;
        __syncthreads();
        const float* mp = g_memnew + (bo + n0 + c)*WW + w;
        #pragma unroll 8
        for (int q = 0; q < 64; q++)
            acc = fmaf(mp[(size_t)q*WW], rw_s[q][r], acc);
    }
    atomicAdd(&out[b*WW*RR + w*RR + r], acc);
}

// ---------------- launch -----------------------------------------------------
extern "C" void kernel_launch(void* const* d_in, const int* in_sizes, int n_in,
                              void* d_out, int out_size) {
    const float* erase_vector    = (const float*)d_in[0];
    const float* free_gates      = (const float*)d_in[1];
    const float* allocation_gate = (const float*)d_in[2];
    const float* write_gate      = (const float*)d_in[3];
    const float* read_modes      = (const float*)d_in[4];
    const float* read_strengths  = (const float*)d_in[5];
    const float* read_keys       = (const float*)d_in[6];
    const float* write_vector    = (const float*)d_in[7];
    const float* write_key       = (const float*)d_in[8];
    const float* write_strength  = (const float*)d_in[9];
    const float* memory          = (const float*)d_in[10];
    const float* read_weightings = (const float*)d_in[11];
    const float* write_weighting = (const float*)d_in[12];
    const float* memory_usage    = (const float*)d_in[13];
    const float* link_matrix     = (const float*)d_in[14];
    const float* precedence      = (const float*)d_in[15];
    float* out = (float*)d_out;

    k1_usage_sim<<<dim3(16, 8), 256>>>(memory, write_key, write_strength, free_gates,
                                       read_weightings, write_weighting, memory_usage, out);
    k2_alloc<<<8, 512>>>();
    k3_ww<<<8, 1024>>>(allocation_gate, write_gate);
    // k6 moved to launch index 3 so ncu's fixed-skip capture lands on it
    k6_link<<<dim3(NN/K6_TM, NN/(K6_CH*K6_NCH), BB), 256>>>(link_matrix, read_weightings, precedence);
    k4_memupdate<<<dim3(16, 8), 256>>>(memory, erase_vector, write_vector,
                                       read_keys, read_strengths);
    k5_cbr<<<dim3(4, 8), 256>>>();
    k7_read<<<dim3(8, 8), 256>>>(read_modes, out);
}